// round 8
// baseline (speedup 1.0000x reference)
#include <cuda_runtime.h>
#include <math.h>

// Fixed dataset shape: B=8, L=512, V=16, K=8.
// out = concat(mask[B,L,V*K], gains[B,L]) as float32.

#define NT 128
#define MAXN 64
#define L_FIXED 512
#define NCHUNK (L_FIXED / 32)
#define CSTRIDE (MAXN + 1)

// Forward-solve a 32-row block for one RHS column j against the RAW (unscaled)
// Cholesky factor: wi' = w[i]/d_i, update w[r] -= Craw[r][i]*wi',
// variance contribution = w[i]*wi'. Zero padding (invd2=0, C pad=0) makes pad
// iterations exact no-ops. Writes wi' to Vb (for raw coupling) and posterior
// stds to W[off+.][j].
__device__ __noinline__ double solve32_block(
    const float (*__restrict__ C)[CSTRIDE],
    float (*__restrict__ W)[CSTRIDE],
    float (*__restrict__ Vb)[CSTRIDE],
    const float* __restrict__ invd2,
    int off, int j, double cum, double osd)
{
    float w[32], wsq[32];
#pragma unroll
    for (int r = 0; r < 32; r++) w[r] = W[off + r][j];
#pragma unroll
    for (int i = 0; i < 32; i++) {
        float wi2 = w[i] * invd2[off + i];
        wsq[i] = w[i] * wi2;                 // = v_i^2 >= 0
        Vb[i][j] = wi2;
#pragma unroll
        for (int r = i + 1; r < 32; r++)
            w[r] -= C[off + r][off + i] * wi2;
    }
    // pairwise fp64 prefix: one chained DADD per 2 elements; stds off-chain
#pragma unroll
    for (int i = 0; i < 32; i += 2) {
        double a = (double)wsq[i];
        double pair = a + (double)wsq[i + 1];
        double ce = cum + a;
        double co = cum + pair;
        W[off + i][j]     = sqrtf(fmaxf((float)(osd - ce), 1e-12f));
        W[off + i + 1][j] = sqrtf(fmaxf((float)(osd - co), 1e-12f));
        cum = co;
    }
    return cum;
}

__global__ __launch_bounds__(NT)
void gp_group_kernel(const float* __restrict__ t,
                     const int* __restrict__ vid,
                     const float* __restrict__ noise,
                     const float* __restrict__ outscale,
                     const float* __restrict__ lenscale,
                     const float* __restrict__ alpha,
                     float* __restrict__ outmask,
                     float* __restrict__ outgains,
                     int B, int L, int V, int K) {
    __shared__ float  C_[MAXN][CSTRIDE];
    __shared__ float  W_[MAXN][CSTRIDE];
    __shared__ float  Vb[32][CSTRIDE];
    __shared__ float  ts[MAXN];
    __shared__ float  tsu[MAXN];
    __shared__ float  invd2[MAXN];
    __shared__ double sums[MAXN];
    __shared__ double warptot[4];
    __shared__ float  dnextS;
    __shared__ int    oidx[MAXN];
    __shared__ int    tmpidx[MAXN];
    __shared__ int    nsh;

    const int v = blockIdx.x;
    const int b = blockIdx.y;
    const int tid = threadIdx.x;
    const int lane = tid & 31;
    const int warp = tid >> 5;

    const float* trow = t + (size_t)b * L_FIXED;
    const int* vrow = vid + (size_t)b * L_FIXED;

    // ---- 0. zero this CTA's mask columns: mask[b, :, v*K .. v*K+7] ----
    {
        float4 z = make_float4(0.f, 0.f, 0.f, 0.f);
        float* base = outmask + ((size_t)b * L_FIXED) * (size_t)(V * K) + (size_t)(v * K);
        #pragma unroll
        for (int l = tid; l < L_FIXED; l += NT) {
            float4* p = (float4*)(base + (size_t)l * (V * K));
            p[0] = z; p[1] = z;
        }
    }

    // ---- 1. order-preserving compaction (warp 0), prefetched loads ----
    if (warp == 0) {
        int   myv[NCHUNK];
        float myt[NCHUNK];
        #pragma unroll
        for (int c = 0; c < NCHUNK; c++) {
            int i = c * 32 + lane;
            myv[c] = vrow[i];
            myt[c] = trow[i];
        }
        int cnt = 0;
        #pragma unroll
        for (int c = 0; c < NCHUNK; c++) {
            bool p = (myv[c] == v);
            unsigned m = __ballot_sync(0xffffffffu, p);
            if (p) {
                int pos = cnt + __popc(m & ((1u << lane) - 1u));
                if (pos < MAXN) {
                    tmpidx[pos] = c * 32 + lane;
                    tsu[pos] = myt[c];
                }
            }
            cnt += __popc(m);
        }
        if (lane == 0) nsh = (cnt < MAXN) ? cnt : MAXN;
    }
    __syncthreads();
    const int n = nsh;
    if (n == 0) return;

    // ---- 2. stable rank sort by time ----
    if (tid < n) {
        float tj = tsu[tid];
        int r = 0;
        #pragma unroll 4
        for (int k2 = 0; k2 < n; k2++) {
            float tk = tsu[k2];
            r += (tk < tj) || (tk == tj && k2 < tid);
        }
        ts[r] = tj;
        oidx[r] = tmpidx[tid];
    }
    __syncthreads();

    const float  os  = outscale[v];
    const float  nz  = noise[v];
    const float  lsv = lenscale[v];
    const float  al  = alpha[v];
    const float  inv2al2 = 1.0f / (2.0f * al * lsv * lsv);
    const double osd = (double)os;

    // ---- 3. fill Kn (C_) and Kxx (W_) over the FULL 64x64, zero padding ----
    for (int idx = tid; idx < MAXN * MAXN; idx += NT) {
        int i = idx >> 6;
        int j = idx & (MAXN - 1);
        if (i < n && j < n) {
            if (i < j) {
                float d = ts[i] - ts[j];
                float kij = os * __expf(-al * __logf(1.0f + d * d * inv2al2));
                C_[i][j] = kij; C_[j][i] = kij;
                W_[i][j] = kij; W_[j][i] = kij;
            } else if (i == j) {
                C_[i][i] = os + nz + 1e-5f;
                W_[i][i] = os;
            }
        } else {
            C_[i][j] = 0.0f;
            W_[i][j] = 0.0f;
        }
    }
    __syncthreads();

    // ---- 4. Cholesky (outer-product, unscaled), register-carried pivots ----
    const int kStartB = (n > 33) ? (n - 33) : 0;
    // Phase A: k in [0, kStartB) -> warps 0-1 (64 threads, thread = row).
    if (warp < 2 && kStartB > 0) {
        const int row = tid;          // 0..63
        float u = (row < n) ? C_[row][0] : 0.0f;   // own column-0 entry
        float dcur = C_[0][0];
        for (int k = 0; k < kStartB; k++) {
            float invd = __fdividef(1.0f, dcur);
            float cik = u * invd;
            float firstnew = 0.0f;
            if (row > k && row < n) {
                #pragma unroll 4
                for (int j = k + 1; j <= row; j++) {
                    float uj = C_[j][k];
                    float nv = C_[row][j] - cik * uj;
                    C_[row][j] = nv;
                    if (j == k + 1) firstnew = nv;
                }
            }
            u = firstnew;                       // own C[row][k+1]
            if (row == k + 1) dnextS = firstnew; // next pivot d_{k+1}
            asm volatile("bar.sync 1, 64;" ::: "memory");
            dcur = dnextS;
        }
    }
    __syncthreads();
    // Phase B: k in [kStartB, n-1) -> warp 0, fixed rows, shfl pivot carry.
    if (warp == 0 && n >= 2) {
        const int rowB = (n > 32) ? (n - 32) : 0;
        const int row = rowB + lane;
        float u = (row < n && row > kStartB - 1) ? C_[row][kStartB] : 0.0f;
        float dcur = C_[kStartB][kStartB];
        for (int k = kStartB; k <= n - 2; k++) {
            float invd = __fdividef(1.0f, dcur);
            float cik = u * invd;
            float firstnew = 0.0f;
            if (row > k && row < n) {
                #pragma unroll 4
                for (int j = k + 1; j <= row; j++) {
                    float uj = C_[j][k];
                    float nv = C_[row][j] - cik * uj;
                    C_[row][j] = nv;
                    if (j == k + 1) firstnew = nv;
                }
            }
            dcur = __shfl_sync(0xffffffffu, firstnew, k + 1 - rowB);
            u = firstnew;
            __syncwarp();
        }
    }
    __syncthreads();
    // invd2[k] = 1/d_k (raw pivot reciprocals); zero padding above n.
    for (int kk = tid; kk < MAXN; kk += NT)
        invd2[kk] = (kk < n) ? __fdividef(1.0f, C_[kk][kk]) : 0.0f;
    __syncthreads();

    // ---- 5. forward solve vs RAW factor, thread-per-column, 32x32 blocks ----
    if (tid < n) {
        const int j = tid;
        double cum = solve32_block(C_, W_, Vb, invd2, 0, j, 0.0, osd);
        if (n > 32) {
            // coupling: residual k2 -= L21_raw @ v'  (v' staged in Vb)
            float w2[32];
            #pragma unroll
            for (int r = 0; r < 32; r++) w2[r] = W_[32 + r][j];
            for (int i = 0; i < 32; i++) {
                float vi = Vb[i][j];
                #pragma unroll
                for (int r = 0; r < 32; r++)
                    w2[r] -= C_[32 + r][i] * vi;
            }
            #pragma unroll
            for (int r = 0; r < 32; r++) W_[32 + r][j] = w2[r];
            cum = solve32_block(C_, W_, Vb, invd2, 32, j, cum, osd);
        }
    }
    __syncthreads();

    // ---- 6. row sums of posterior stds (W_ already holds stds) ----
    for (int i = tid; i < n; i += NT) {
        double a0 = 0.0, a1 = 0.0, a2 = 0.0, a3 = 0.0;
        int j = 0;
        for (; j + 3 < n; j += 4) {
            a0 += (double)W_[i][j];
            a1 += (double)W_[i][j + 1];
            a2 += (double)W_[i][j + 2];
            a3 += (double)W_[i][j + 3];
        }
        for (; j < n; j++) a0 += (double)W_[i][j];
        sums[i] = (a0 + a1) + (a2 + a3);
    }
    __syncthreads();

    // ---- 7. gains + block-wide fp64 inclusive scan (shuffles) ----
    double g = 0.0;
    if (tid < n) {
        double prevs = (tid == 0) ? sqrt(osd) * (double)n : sums[tid - 1];
        g = prevs - sums[tid];
        if (g < 0.0) g = 0.0;
    }
    double x = g;
    #pragma unroll
    for (int off = 1; off < 32; off <<= 1) {
        double y = __shfl_up_sync(0xffffffffu, x, off);
        if (lane >= off) x += y;
    }
    if (lane == 31) warptot[warp] = x;
    __syncthreads();
    double woff = 0.0;
    for (int w2i = 0; w2i < warp; w2i++) woff += warptot[w2i];
    x += woff;
    double totcg = (warptot[0] + warptot[1]) + (warptot[2] + warptot[3]);
    if (totcg < 1e-12) totcg = 1e-12;

    // ---- 8. group assignment + scatter ----
    if (tid < n) {
        double frac = (x - 0.5 * g) / totcg;
        int gbin = (int)floor(frac * (double)K);
        gbin = gbin < 0 ? 0 : (gbin > K - 1 ? K - 1 : gbin);
        int l = oidx[tid];
        size_t row = (size_t)(b * L_FIXED + l);
        outmask[row * (size_t)(V * K) + (size_t)(v * K + gbin)] = 1.0f;
        outgains[row] = (float)g;
    }
}

extern "C" void kernel_launch(void* const* d_in, const int* in_sizes, int n_in,
                              void* d_out, int out_size) {
    const float* t       = (const float*)d_in[0];
    const int*   vid     = (const int*)d_in[2];
    const float* noise   = (const float*)d_in[3];
    const float* outsc   = (const float*)d_in[4];
    const float* lensc   = (const float*)d_in[5];
    const float* alph    = (const float*)d_in[6];

    int BL = in_sizes[0];            // B*L
    int V  = in_sizes[3];
    int L  = L_FIXED;
    int B  = BL / L;
    int VK1 = out_size / BL;         // V*K + 1
    int K  = (VK1 - 1) / V;

    float* outp  = (float*)d_out;
    float* gains = outp + (size_t)BL * (size_t)(VK1 - 1);

    dim3 grid(V, B);
    gp_group_kernel<<<grid, NT>>>(t, vid, noise, outsc, lensc, alph,
                                  outp, gains, B, L, V, K);
}

// round 9
// speedup vs baseline: 1.8596x; 1.8596x over previous
#include <cuda_runtime.h>
#include <math.h>

// Fixed dataset shape: B=8, L=512, V=16, K=8.
// out = concat(mask[B,L,V*K], gains[B,L]) as float32.

#define NT 128
#define MAXN 64
#define L_FIXED 512
#define NCHUNK (L_FIXED / 32)
#define CSTRIDE (MAXN + 1)

// Forward-solve a 32-row block for one RHS column j against the RAW (LDL-style)
// factor: wi2 = w[i]/d_i, v_i^2 = w[i]*wi2, update w[r] -= Craw[r][i]*wi2.
// Zero padding (invd2=0, C pad=0) makes pad iterations exact no-ops.
// cum carried as Kahan-compensated fp32 pair (s, c), pairwise (2 elems/link).
// Writes wi2 to Vb (for raw coupling) and posterior stds to W[off+.][j].
__device__ __noinline__ float2 solve32_block(
    const float (*__restrict__ C)[CSTRIDE],
    float (*__restrict__ W)[CSTRIDE],
    float (*__restrict__ Vb)[CSTRIDE],
    const float* __restrict__ invd2,
    int off, int j, float2 sc, float os)
{
    float w[32], wsq[32];
#pragma unroll
    for (int r = 0; r < 32; r++) w[r] = W[off + r][j];
#pragma unroll
    for (int i = 0; i < 32; i++) {
        float wi2 = w[i] * invd2[off + i];
        wsq[i] = w[i] * wi2;                 // = v_i^2 >= 0
        Vb[i][j] = wi2;
#pragma unroll
        for (int r = i + 1; r < 32; r++)
            w[r] -= C[off + r][off + i] * wi2;
    }
    float s = sc.x, c = sc.y;
#pragma unroll
    for (int i = 0; i < 32; i += 2) {
        float a = wsq[i];
        float pair = a + wsq[i + 1];         // off-chain
        float ce = s + (c + a);              // even prefix estimate
        float yy = c + pair;
        float tt = s + yy;
        c = (s - tt) + yy;                   // Kahan compensation
        s = tt;
        W[off + i][j]     = sqrtf(fmaxf(os - ce, 1e-12f));
        W[off + i + 1][j] = sqrtf(fmaxf(os - (s + c), 1e-12f));
    }
    return make_float2(s, c);
}

__global__ __launch_bounds__(NT)
void gp_group_kernel(const float* __restrict__ t,
                     const int* __restrict__ vid,
                     const float* __restrict__ noise,
                     const float* __restrict__ outscale,
                     const float* __restrict__ lenscale,
                     const float* __restrict__ alpha,
                     float* __restrict__ outmask,
                     float* __restrict__ outgains,
                     int B, int L, int V, int K) {
    __shared__ float  C_[MAXN][CSTRIDE];
    __shared__ float  W_[MAXN][CSTRIDE];
    __shared__ float  Vb[32][CSTRIDE];
    __shared__ float  ts[MAXN];
    __shared__ float  tsu[MAXN];
    __shared__ float  invd2[MAXN];
    __shared__ double sums[MAXN];
    __shared__ double warptot[4];
    __shared__ int    oidx[MAXN];
    __shared__ int    tmpidx[MAXN];
    __shared__ int    nsh;

    const int v = blockIdx.x;
    const int b = blockIdx.y;
    const int tid = threadIdx.x;
    const int lane = tid & 31;
    const int warp = tid >> 5;

    const float* trow = t + (size_t)b * L_FIXED;
    const int* vrow = vid + (size_t)b * L_FIXED;

    // ---- 0. zero this CTA's mask columns: mask[b, :, v*K .. v*K+7] ----
    {
        float4 z = make_float4(0.f, 0.f, 0.f, 0.f);
        float* base = outmask + ((size_t)b * L_FIXED) * (size_t)(V * K) + (size_t)(v * K);
        #pragma unroll
        for (int l = tid; l < L_FIXED; l += NT) {
            float4* p = (float4*)(base + (size_t)l * (V * K));
            p[0] = z; p[1] = z;
        }
    }

    // ---- 1. order-preserving compaction (warp 0), prefetched loads ----
    if (warp == 0) {
        int   myv[NCHUNK];
        float myt[NCHUNK];
        #pragma unroll
        for (int c = 0; c < NCHUNK; c++) {
            int i = c * 32 + lane;
            myv[c] = vrow[i];
            myt[c] = trow[i];
        }
        int cnt = 0;
        #pragma unroll
        for (int c = 0; c < NCHUNK; c++) {
            bool p = (myv[c] == v);
            unsigned m = __ballot_sync(0xffffffffu, p);
            if (p) {
                int pos = cnt + __popc(m & ((1u << lane) - 1u));
                if (pos < MAXN) {
                    tmpidx[pos] = c * 32 + lane;
                    tsu[pos] = myt[c];
                }
            }
            cnt += __popc(m);
        }
        if (lane == 0) nsh = (cnt < MAXN) ? cnt : MAXN;
    }
    __syncthreads();
    const int n = nsh;
    if (n == 0) return;

    // ---- 2. stable rank sort by time ----
    if (tid < n) {
        float tj = tsu[tid];
        int r = 0;
        #pragma unroll 4
        for (int k2 = 0; k2 < n; k2++) {
            float tk = tsu[k2];
            r += (tk < tj) || (tk == tj && k2 < tid);
        }
        ts[r] = tj;
        oidx[r] = tmpidx[tid];
    }
    __syncthreads();

    const float  os  = outscale[v];
    const float  nz  = noise[v];
    const float  lsv = lenscale[v];
    const float  al  = alpha[v];
    const float  inv2al2 = 1.0f / (2.0f * al * lsv * lsv);
    const double osd = (double)os;

    // ---- 3. fill Kn (C_) and Kxx (W_) over the FULL 64x64, zero padding ----
    for (int idx = tid; idx < MAXN * MAXN; idx += NT) {
        int i = idx >> 6;
        int j = idx & (MAXN - 1);
        if (i < n && j < n) {
            if (i < j) {
                float d = ts[i] - ts[j];
                float kij = os * __expf(-al * __logf(1.0f + d * d * inv2al2));
                C_[i][j] = kij; C_[j][i] = kij;
                W_[i][j] = kij; W_[j][i] = kij;
            } else if (i == j) {
                C_[i][i] = os + nz + 1e-5f;
                W_[i][i] = os;
            }
        } else {
            C_[i][j] = 0.0f;
            W_[i][j] = 0.0f;
        }
    }
    __syncthreads();

    // ---- 4. Cholesky (outer-product, unscaled) — R7 known-good form ----
    // Phase A: >32 active rows -> warps 0-1 (64 threads), named barrier.
    if (warp < 2) {
        int t64 = tid;           // 0..63
        for (int k = 0; k < n - 1 && (n - 1 - k) > 32; k++) {
            float invd = __fdividef(1.0f, C_[k][k]);
            int i = k + 1 + t64;
            if (i < n) {
                float cik = C_[i][k] * invd;
                #pragma unroll 4
                for (int j = k + 1; j <= i; j++)
                    C_[i][j] -= cik * C_[j][k];
            }
            asm volatile("bar.sync 1, 64;" ::: "memory");
        }
    }
    // Phase B: last <=32 steps -> warp 0 only, __syncwarp.
    if (warp == 0) {
        for (int k = (n > 33 ? n - 33 : 0); k < n - 1; k++) {
            float invd = __fdividef(1.0f, C_[k][k]);
            int i = k + 1 + lane;
            if (i < n) {
                float cik = C_[i][k] * invd;
                #pragma unroll 4
                for (int j = k + 1; j <= i; j++)
                    C_[i][j] -= cik * C_[j][k];
            }
            __syncwarp();
        }
    }
    __syncthreads();
    // invd2[k] = 1/d_k (raw pivot reciprocals); zero padding above n.
    for (int kk = tid; kk < MAXN; kk += NT)
        invd2[kk] = (kk < n) ? __fdividef(1.0f, C_[kk][kk]) : 0.0f;
    __syncthreads();

    // ---- 5. forward solve vs RAW factor, thread-per-column, 32x32 blocks ----
    if (tid < n) {
        const int j = tid;
        float2 sc = solve32_block(C_, W_, Vb, invd2, 0, j,
                                  make_float2(0.0f, 0.0f), os);
        if (n > 32) {
            // coupling: residual k2 -= L21_raw @ v'  (v' staged in Vb)
            float w2[32];
            #pragma unroll
            for (int r = 0; r < 32; r++) w2[r] = W_[32 + r][j];
            for (int i = 0; i < 32; i++) {
                float vi = Vb[i][j];
                #pragma unroll
                for (int r = 0; r < 32; r++)
                    w2[r] -= C_[32 + r][i] * vi;
            }
            #pragma unroll
            for (int r = 0; r < 32; r++) W_[32 + r][j] = w2[r];
            solve32_block(C_, W_, Vb, invd2, 32, j, sc, os);
        }
    }
    __syncthreads();

    // ---- 6. row sums of posterior stds (W_ already holds stds) ----
    for (int i = tid; i < n; i += NT) {
        double a0 = 0.0, a1 = 0.0, a2 = 0.0, a3 = 0.0;
        int j = 0;
        for (; j + 3 < n; j += 4) {
            a0 += (double)W_[i][j];
            a1 += (double)W_[i][j + 1];
            a2 += (double)W_[i][j + 2];
            a3 += (double)W_[i][j + 3];
        }
        for (; j < n; j++) a0 += (double)W_[i][j];
        sums[i] = (a0 + a1) + (a2 + a3);
    }
    __syncthreads();

    // ---- 7. gains + block-wide fp64 inclusive scan (shuffles) ----
    double g = 0.0;
    if (tid < n) {
        double prevs = (tid == 0) ? sqrt(osd) * (double)n : sums[tid - 1];
        g = prevs - sums[tid];
        if (g < 0.0) g = 0.0;
    }
    double x = g;
    #pragma unroll
    for (int off = 1; off < 32; off <<= 1) {
        double y = __shfl_up_sync(0xffffffffu, x, off);
        if (lane >= off) x += y;
    }
    if (lane == 31) warptot[warp] = x;
    __syncthreads();
    double woff = 0.0;
    for (int w2i = 0; w2i < warp; w2i++) woff += warptot[w2i];
    x += woff;
    double totcg = (warptot[0] + warptot[1]) + (warptot[2] + warptot[3]);
    if (totcg < 1e-12) totcg = 1e-12;

    // ---- 8. group assignment + scatter ----
    if (tid < n) {
        double frac = (x - 0.5 * g) / totcg;
        int gbin = (int)floor(frac * (double)K);
        gbin = gbin < 0 ? 0 : (gbin > K - 1 ? K - 1 : gbin);
        int l = oidx[tid];
        size_t row = (size_t)(b * L_FIXED + l);
        outmask[row * (size_t)(V * K) + (size_t)(v * K + gbin)] = 1.0f;
        outgains[row] = (float)g;
    }
}

extern "C" void kernel_launch(void* const* d_in, const int* in_sizes, int n_in,
                              void* d_out, int out_size) {
    const float* t       = (const float*)d_in[0];
    const int*   vid     = (const int*)d_in[2];
    const float* noise   = (const float*)d_in[3];
    const float* outsc   = (const float*)d_in[4];
    const float* lensc   = (const float*)d_in[5];
    const float* alph    = (const float*)d_in[6];

    int BL = in_sizes[0];            // B*L
    int V  = in_sizes[3];
    int L  = L_FIXED;
    int B  = BL / L;
    int VK1 = out_size / BL;         // V*K + 1
    int K  = (VK1 - 1) / V;

    float* outp  = (float*)d_out;
    float* gains = outp + (size_t)BL * (size_t)(VK1 - 1);

    dim3 grid(V, B);
    gp_group_kernel<<<grid, NT>>>(t, vid, noise, outsc, lensc, alph,
                                  outp, gains, B, L, V, K);
}

// round 12
// speedup vs baseline: 2.0205x; 1.0865x over previous
#include <cuda_runtime.h>
#include <math.h>

// Fixed dataset shape: B=8, L=512, V=16, K=8.
// out = concat(mask[B,L,V*K], gains[B,L]) as float32.

#define NT 128
#define MAXN 64
#define L_FIXED 512
#define NCHUNK (L_FIXED / 32)
#define CSTRIDE (MAXN + 1)

// Forward-solve a 32-row block for one RHS column j against the RAW (LDL-style)
// factor: wi2 = w[i]/d_i, v_i^2 = w[i]*wi2, update w[r] -= Craw[r][i]*wi2.
// Zero padding (invd2=0, C pad=0) makes pad iterations exact no-ops.
// cum carried as Kahan-compensated fp32 pair (s, c), pairwise (2 elems/link).
// Writes wi2 to Vb (for raw coupling) and posterior stds to W[off+.][j].
__device__ __noinline__ float2 solve32_block(
    const float (*__restrict__ C)[CSTRIDE],
    float (*__restrict__ W)[CSTRIDE],
    float (*__restrict__ Vb)[CSTRIDE],
    const float* __restrict__ invd2,
    int off, int j, float2 sc, float os)
{
    float w[32], wsq[32];
#pragma unroll
    for (int r = 0; r < 32; r++) w[r] = W[off + r][j];
#pragma unroll
    for (int i = 0; i < 32; i++) {
        float wi2 = w[i] * invd2[off + i];
        wsq[i] = w[i] * wi2;                 // = v_i^2 >= 0
        Vb[i][j] = wi2;
#pragma unroll
        for (int r = i + 1; r < 32; r++)
            w[r] -= C[off + r][off + i] * wi2;
    }
    float s = sc.x, c = sc.y;
#pragma unroll
    for (int i = 0; i < 32; i += 2) {
        float a = wsq[i];
        float pair = a + wsq[i + 1];         // off-chain
        float ce = s + (c + a);              // even prefix estimate
        float yy = c + pair;
        float tt = s + yy;
        c = (s - tt) + yy;                   // Kahan compensation
        s = tt;
        W[off + i][j]     = sqrtf(fmaxf(os - ce, 1e-12f));
        W[off + i + 1][j] = sqrtf(fmaxf(os - (s + c), 1e-12f));
    }
    return make_float2(s, c);
}

__global__ __launch_bounds__(NT)
void gp_group_kernel(const float* __restrict__ t,
                     const int* __restrict__ vid,
                     const float* __restrict__ noise,
                     const float* __restrict__ outscale,
                     const float* __restrict__ lenscale,
                     const float* __restrict__ alpha,
                     float* __restrict__ outmask,
                     float* __restrict__ outgains,
                     int B, int L, int V, int K) {
    __shared__ float  C_[MAXN][CSTRIDE];
    __shared__ float  W_[MAXN][CSTRIDE];
    __shared__ float  Vb[32][CSTRIDE];
    __shared__ float  ts[MAXN];
    __shared__ float  tsu[MAXN];
    __shared__ float  invd2[MAXN];
    __shared__ double sums[MAXN];
    __shared__ double warptot[4];
    __shared__ int    oidx[MAXN];
    __shared__ int    tmpidx[MAXN];
    __shared__ int    nsh;

    const int v = blockIdx.x;
    const int b = blockIdx.y;
    const int tid = threadIdx.x;
    const int lane = tid & 31;
    const int warp = tid >> 5;

    const float* trow = t + (size_t)b * L_FIXED;
    const int* vrow = vid + (size_t)b * L_FIXED;

    // ---- 0. zero this CTA's mask columns: mask[b, :, v*K .. v*K+7] ----
    {
        float4 z = make_float4(0.f, 0.f, 0.f, 0.f);
        float* base = outmask + ((size_t)b * L_FIXED) * (size_t)(V * K) + (size_t)(v * K);
        #pragma unroll
        for (int l = tid; l < L_FIXED; l += NT) {
            float4* p = (float4*)(base + (size_t)l * (V * K));
            p[0] = z; p[1] = z;
        }
    }

    // ---- 1. order-preserving compaction (warp 0), prefetched loads ----
    if (warp == 0) {
        int   myv[NCHUNK];
        float myt[NCHUNK];
        #pragma unroll
        for (int c = 0; c < NCHUNK; c++) {
            int i = c * 32 + lane;
            myv[c] = vrow[i];
            myt[c] = trow[i];
        }
        int cnt = 0;
        #pragma unroll
        for (int c = 0; c < NCHUNK; c++) {
            bool p = (myv[c] == v);
            unsigned m = __ballot_sync(0xffffffffu, p);
            if (p) {
                int pos = cnt + __popc(m & ((1u << lane) - 1u));
                if (pos < MAXN) {
                    tmpidx[pos] = c * 32 + lane;
                    tsu[pos] = myt[c];
                }
            }
            cnt += __popc(m);
        }
        if (lane == 0) nsh = (cnt < MAXN) ? cnt : MAXN;
    }
    __syncthreads();
    const int n = nsh;
    if (n == 0) return;

    // ---- 2. stable rank sort by time ----
    if (tid < n) {
        float tj = tsu[tid];
        int r = 0;
        #pragma unroll 4
        for (int k2 = 0; k2 < n; k2++) {
            float tk = tsu[k2];
            r += (tk < tj) || (tk == tj && k2 < tid);
        }
        ts[r] = tj;
        oidx[r] = tmpidx[tid];
    }
    __syncthreads();

    const float  os  = outscale[v];
    const float  nz  = noise[v];
    const float  lsv = lenscale[v];
    const float  al  = alpha[v];
    const float  inv2al2 = 1.0f / (2.0f * al * lsv * lsv);
    const double osd = (double)os;

    // ---- 3. fill Kn (C_) and Kxx (W_) over the FULL 64x64, zero padding ----
    for (int idx = tid; idx < MAXN * MAXN; idx += NT) {
        int i = idx >> 6;
        int j = idx & (MAXN - 1);
        if (i < n && j < n) {
            if (i < j) {
                float d = ts[i] - ts[j];
                float kij = os * __expf(-al * __logf(1.0f + d * d * inv2al2));
                C_[i][j] = kij; C_[j][i] = kij;
                W_[i][j] = kij; W_[j][i] = kij;
            } else if (i == j) {
                C_[i][i] = os + nz + 1e-5f;
                W_[i][i] = os;
            }
        } else {
            C_[i][j] = 0.0f;
            W_[i][j] = 0.0f;
        }
    }
    __syncthreads();

    // ---- 4/5. Cholesky + forward solve, warp-specialized overlap ----
    // Stage 1: steps with >32 active rows -> warps 0-1 (64 threads).
    if (warp < 2) {
        for (int k = 0; k < n - 33; k++) {
            float invd = __fdividef(1.0f, C_[k][k]);
            int i = k + 1 + tid;
            if (i < n) {
                float cik = C_[i][k] * invd;
                #pragma unroll 4
                for (int j = k + 1; j <= i; j++)
                    C_[i][j] -= cik * C_[j][k];
            }
            asm volatile("bar.sync 1, 64;" ::: "memory");
        }
    }
    // Stage 2: steps up to k=31 (<=32 active rows) -> warp 0 only.
    if (warp == 0) {
        const int kStart2 = (n > 33) ? (n - 33) : 0;
        const int kEnd2   = (n > 32) ? 31 : (n - 2);
        for (int k = kStart2; k <= kEnd2; k++) {
            float invd = __fdividef(1.0f, C_[k][k]);
            int i = k + 1 + lane;
            if (i < n) {
                float cik = C_[i][k] * invd;
                #pragma unroll 4
                for (int j = k + 1; j <= i; j++)
                    C_[i][j] -= cik * C_[j][k];
            }
            __syncwarp();
        }
    }
    // Leading 32x32 factor final -> warps 0,2,3 rendezvous. Warp 1 exits to
    // the convergent __syncthreads below.
    if (warp != 1) {
        asm volatile("bar.sync 2, 96;" ::: "memory");
    }
    if (warp == 0) {
        // Stage 3 (concurrent with solve block 1): tail steps k=32..n-2.
        if (n > 32) {
            for (int k = 32; k <= n - 2; k++) {
                float invd = __fdividef(1.0f, C_[k][k]);
                int i = k + 1 + lane;
                if (i < n) {
                    float cik = C_[i][k] * invd;
                    #pragma unroll 4
                    for (int j = k + 1; j <= i; j++)
                        C_[i][j] -= cik * C_[j][k];
                }
                __syncwarp();
            }
            int kk = 32 + lane;
            invd2[kk] = (kk < n) ? __fdividef(1.0f, C_[kk][kk]) : 0.0f;
            asm volatile("bar.sync 3, 96;" ::: "memory");
        }
    } else if (warp >= 2) {
        const int j = tid - 64;                   // solve column
        if (warp == 2)
            invd2[lane] = (lane < n) ? __fdividef(1.0f, C_[lane][lane]) : 0.0f;
        asm volatile("bar.sync 4, 64;" ::: "memory");   // warps 2-3
        float2 sc = make_float2(0.0f, 0.0f);
        if (j < n)
            sc = solve32_block(C_, W_, Vb, invd2, 0, j, sc, os);
        if (n > 32) {
            if (j < n) {
                // coupling: residual k2 -= L21_raw @ v' (v' staged in Vb)
                float w2[32];
                #pragma unroll
                for (int r = 0; r < 32; r++) w2[r] = W_[32 + r][j];
                for (int i = 0; i < 32; i++) {
                    float vi = Vb[i][j];
                    #pragma unroll
                    for (int r = 0; r < 32; r++)
                        w2[r] -= C_[32 + r][i] * vi;
                }
                #pragma unroll
                for (int r = 0; r < 32; r++) W_[32 + r][j] = w2[r];
            }
            asm volatile("bar.sync 3, 96;" ::: "memory");  // factor+coupling done
            if (j < n)
                solve32_block(C_, W_, Vb, invd2, 32, j, sc, os);
        }
    }
    __syncthreads();

    // ---- 6. row sums of posterior stds (8-way fp64 accumulators) ----
    for (int i = tid; i < n; i += NT) {
        double a0 = 0.0, a1 = 0.0, a2 = 0.0, a3 = 0.0;
        double a4 = 0.0, a5 = 0.0, a6 = 0.0, a7 = 0.0;
        int j = 0;
        for (; j + 7 < n; j += 8) {
            a0 += (double)W_[i][j];
            a1 += (double)W_[i][j + 1];
            a2 += (double)W_[i][j + 2];
            a3 += (double)W_[i][j + 3];
            a4 += (double)W_[i][j + 4];
            a5 += (double)W_[i][j + 5];
            a6 += (double)W_[i][j + 6];
            a7 += (double)W_[i][j + 7];
        }
        for (; j < n; j++) a0 += (double)W_[i][j];
        sums[i] = ((a0 + a1) + (a2 + a3)) + ((a4 + a5) + (a6 + a7));
    }
    __syncthreads();

    // ---- 7. gains + block-wide fp64 inclusive scan (shuffles) ----
    double g = 0.0;
    if (tid < n) {
        double prevs = (tid == 0) ? sqrt(osd) * (double)n : sums[tid - 1];
        g = prevs - sums[tid];
        if (g < 0.0) g = 0.0;
    }
    double x = g;
    #pragma unroll
    for (int off = 1; off < 32; off <<= 1) {
        double y = __shfl_up_sync(0xffffffffu, x, off);
        if (lane >= off) x += y;
    }
    if (lane == 31) warptot[warp] = x;
    __syncthreads();
    double woff = 0.0;
    for (int w2i = 0; w2i < warp; w2i++) woff += warptot[w2i];
    x += woff;
    double totcg = (warptot[0] + warptot[1]) + (warptot[2] + warptot[3]);
    if (totcg < 1e-12) totcg = 1e-12;

    // ---- 8. group assignment + scatter ----
    if (tid < n) {
        double frac = (x - 0.5 * g) / totcg;
        int gbin = (int)floor(frac * (double)K);
        gbin = gbin < 0 ? 0 : (gbin > K - 1 ? K - 1 : gbin);
        int l = oidx[tid];
        size_t row = (size_t)(b * L_FIXED + l);
        outmask[row * (size_t)(V * K) + (size_t)(v * K + gbin)] = 1.0f;
        outgains[row] = (float)g;
    }
}

extern "C" void kernel_launch(void* const* d_in, const int* in_sizes, int n_in,
                              void* d_out, int out_size) {
    const float* t       = (const float*)d_in[0];
    const int*   vid     = (const int*)d_in[2];
    const float* noise   = (const float*)d_in[3];
    const float* outsc   = (const float*)d_in[4];
    const float* lensc   = (const float*)d_in[5];
    const float* alph    = (const float*)d_in[6];

    int BL = in_sizes[0];            // B*L
    int V  = in_sizes[3];
    int L  = L_FIXED;
    int B  = BL / L;
    int VK1 = out_size / BL;         // V*K + 1
    int K  = (VK1 - 1) / V;

    float* outp  = (float*)d_out;
    float* gains = outp + (size_t)BL * (size_t)(VK1 - 1);

    dim3 grid(V, B);
    gp_group_kernel<<<grid, NT>>>(t, vid, noise, outsc, lensc, alph,
                                  outp, gains, B, L, V, K);
}

// round 15
// speedup vs baseline: 2.0322x; 1.0058x over previous
#include <cuda_runtime.h>
#include <math.h>

// Fixed dataset shape: B=8, L=512, V=16, K=8.
// out = concat(mask[B,L,V*K], gains[B,L]) as float32.

#define NT 256
#define NWARP (NT / 32)
#define MAXN 64
#define L_FIXED 512
#define NCHUNK (L_FIXED / 32)
#define CSTRIDE (MAXN + 1)

// Forward-solve a 32-row block for one RHS column j against the RAW (LDL-style)
// factor: wi2 = w[i]/d_i, v_i^2 = w[i]*wi2, update w[r] -= Craw[r][i]*wi2.
// Zero padding (invd2=0, C pad=0) makes pad iterations exact no-ops.
// cum carried as Kahan-compensated fp32 pair (s, c), pairwise (2 elems/link).
// Writes wi2 to Vb (for raw coupling) and posterior stds to W[off+.][j].
__device__ __noinline__ float2 solve32_block(
    const float (*__restrict__ C)[CSTRIDE],
    float (*__restrict__ W)[CSTRIDE],
    float (*__restrict__ Vb)[CSTRIDE],
    const float* __restrict__ invd2,
    int off, int j, float2 sc, float os)
{
    float w[32], wsq[32];
#pragma unroll
    for (int r = 0; r < 32; r++) w[r] = W[off + r][j];
#pragma unroll
    for (int i = 0; i < 32; i++) {
        float wi2 = w[i] * invd2[off + i];
        wsq[i] = w[i] * wi2;                 // = v_i^2 >= 0
        Vb[i][j] = wi2;
#pragma unroll
        for (int r = i + 1; r < 32; r++)
            w[r] -= C[off + r][off + i] * wi2;
    }
    float s = sc.x, c = sc.y;
#pragma unroll
    for (int i = 0; i < 32; i += 2) {
        float a = wsq[i];
        float pair = a + wsq[i + 1];         // off-chain
        float ce = s + (c + a);              // even prefix estimate
        float yy = c + pair;
        float tt = s + yy;
        c = (s - tt) + yy;                   // Kahan compensation
        s = tt;
        W[off + i][j]     = sqrtf(fmaxf(os - ce, 1e-12f));
        W[off + i + 1][j] = sqrtf(fmaxf(os - (s + c), 1e-12f));
    }
    return make_float2(s, c);
}

__global__ __launch_bounds__(NT)
void gp_group_kernel(const float* __restrict__ t,
                     const int* __restrict__ vid,
                     const float* __restrict__ noise,
                     const float* __restrict__ outscale,
                     const float* __restrict__ lenscale,
                     const float* __restrict__ alpha,
                     float* __restrict__ outmask,
                     float* __restrict__ outgains,
                     int B, int L, int V, int K) {
    __shared__ float  C_[MAXN][CSTRIDE];
    __shared__ float  W_[MAXN][CSTRIDE];
    __shared__ float  Vb[32][CSTRIDE];
    __shared__ float  ts[MAXN];
    __shared__ float  tsu[MAXN];
    __shared__ float  invd2[MAXN];
    __shared__ double sums[MAXN];
    __shared__ double warptot[NWARP];
    __shared__ int    oidx[MAXN];
    __shared__ int    tmpidx[MAXN];
    __shared__ int    nsh;

    const int v = blockIdx.x;
    const int b = blockIdx.y;
    const int tid = threadIdx.x;
    const int lane = tid & 31;
    const int warp = tid >> 5;

    const float* trow = t + (size_t)b * L_FIXED;
    const int* vrow = vid + (size_t)b * L_FIXED;

    // ---- 0. zero this CTA's mask columns: mask[b, :, v*K .. v*K+7] ----
    {
        float4 z = make_float4(0.f, 0.f, 0.f, 0.f);
        float* base = outmask + ((size_t)b * L_FIXED) * (size_t)(V * K) + (size_t)(v * K);
        #pragma unroll
        for (int l = tid; l < L_FIXED; l += NT) {
            float4* p = (float4*)(base + (size_t)l * (V * K));
            p[0] = z; p[1] = z;
        }
    }

    // ---- 1. order-preserving compaction (warp 0), prefetched loads ----
    if (warp == 0) {
        int   myv[NCHUNK];
        float myt[NCHUNK];
        #pragma unroll
        for (int c = 0; c < NCHUNK; c++) {
            int i = c * 32 + lane;
            myv[c] = vrow[i];
            myt[c] = trow[i];
        }
        int cnt = 0;
        #pragma unroll
        for (int c = 0; c < NCHUNK; c++) {
            bool p = (myv[c] == v);
            unsigned m = __ballot_sync(0xffffffffu, p);
            if (p) {
                int pos = cnt + __popc(m & ((1u << lane) - 1u));
                if (pos < MAXN) {
                    tmpidx[pos] = c * 32 + lane;
                    tsu[pos] = myt[c];
                }
            }
            cnt += __popc(m);
        }
        if (lane == 0) nsh = (cnt < MAXN) ? cnt : MAXN;
    }
    __syncthreads();
    const int n = nsh;
    if (n == 0) return;

    // ---- 2. stable rank sort by time ----
    if (tid < n) {
        float tj = tsu[tid];
        int r = 0;
        #pragma unroll 4
        for (int k2 = 0; k2 < n; k2++) {
            float tk = tsu[k2];
            r += (tk < tj) || (tk == tj && k2 < tid);
        }
        ts[r] = tj;
        oidx[r] = tmpidx[tid];
    }
    __syncthreads();

    const float  os  = outscale[v];
    const float  nz  = noise[v];
    const float  lsv = lenscale[v];
    const float  al  = alpha[v];
    const float  inv2al2 = 1.0f / (2.0f * al * lsv * lsv);
    const double osd = (double)os;

    // ---- 3. fill Kn (C_) and Kxx (W_) over the FULL 64x64, zero padding ----
    for (int idx = tid; idx < MAXN * MAXN; idx += NT) {
        int i = idx >> 6;
        int j = idx & (MAXN - 1);
        if (i < n && j < n) {
            if (i < j) {
                float d = ts[i] - ts[j];
                float kij = os * __expf(-al * __logf(1.0f + d * d * inv2al2));
                C_[i][j] = kij; C_[j][i] = kij;
                W_[i][j] = kij; W_[j][i] = kij;
            } else if (i == j) {
                C_[i][i] = os + nz + 1e-5f;
                W_[i][i] = os;
            }
        } else {
            C_[i][j] = 0.0f;
            W_[i][j] = 0.0f;
        }
    }
    __syncthreads();

    // ---- 4/5. Cholesky + forward solve, warp-specialized overlap ----
    // Stage 1: steps with >32 active rows -> warps 0-1 (64 threads).
    if (warp < 2) {
        for (int k = 0; k < n - 33; k++) {
            float invd = __fdividef(1.0f, C_[k][k]);
            int i = k + 1 + tid;
            if (i < n) {
                float cik = C_[i][k] * invd;
                #pragma unroll 4
                for (int j = k + 1; j <= i; j++)
                    C_[i][j] -= cik * C_[j][k];
            }
            asm volatile("bar.sync 1, 64;" ::: "memory");
        }
    }
    // Stage 2: steps up to k=31 (<=32 active rows) -> warp 0 only.
    if (warp == 0) {
        const int kStart2 = (n > 33) ? (n - 33) : 0;
        const int kEnd2   = (n > 32) ? 31 : (n - 2);
        for (int k = kStart2; k <= kEnd2; k++) {
            float invd = __fdividef(1.0f, C_[k][k]);
            int i = k + 1 + lane;
            if (i < n) {
                float cik = C_[i][k] * invd;
                #pragma unroll 4
                for (int j = k + 1; j <= i; j++)
                    C_[i][j] -= cik * C_[j][k];
            }
            __syncwarp();
        }
    }
    // Leading 32x32 factor final -> warps 0,2,3 rendezvous (96 threads).
    // Warps 1 and 4-7 go to the convergent __syncthreads below.
    if (warp < 4 && warp != 1) {
        asm volatile("bar.sync 2, 96;" ::: "memory");
    }
    if (warp == 0) {
        // Stage 3 (concurrent with solve block 1): tail steps k=32..n-2.
        if (n > 32) {
            for (int k = 32; k <= n - 2; k++) {
                float invd = __fdividef(1.0f, C_[k][k]);
                int i = k + 1 + lane;
                if (i < n) {
                    float cik = C_[i][k] * invd;
                    #pragma unroll 4
                    for (int j = k + 1; j <= i; j++)
                        C_[i][j] -= cik * C_[j][k];
                }
                __syncwarp();
            }
            int kk = 32 + lane;
            invd2[kk] = (kk < n) ? __fdividef(1.0f, C_[kk][kk]) : 0.0f;
            asm volatile("bar.sync 3, 96;" ::: "memory");
        }
    } else if (warp == 2 || warp == 3) {
        const int j = tid - 64;                   // solve column
        if (warp == 2)
            invd2[lane] = (lane < n) ? __fdividef(1.0f, C_[lane][lane]) : 0.0f;
        asm volatile("bar.sync 4, 64;" ::: "memory");   // warps 2-3
        float2 sc = make_float2(0.0f, 0.0f);
        if (j < n)
            sc = solve32_block(C_, W_, Vb, invd2, 0, j, sc, os);
        if (n > 32) {
            if (j < n) {
                // coupling: residual k2 -= L21_raw @ v' (v' staged in Vb)
                float w2[32];
                #pragma unroll
                for (int r = 0; r < 32; r++) w2[r] = W_[32 + r][j];
                for (int i = 0; i < 32; i++) {
                    float vi = Vb[i][j];
                    #pragma unroll
                    for (int r = 0; r < 32; r++)
                        w2[r] -= C_[32 + r][i] * vi;
                }
                #pragma unroll
                for (int r = 0; r < 32; r++) W_[32 + r][j] = w2[r];
            }
            asm volatile("bar.sync 3, 96;" ::: "memory");  // factor+coupling done
            if (j < n)
                solve32_block(C_, W_, Vb, invd2, 32, j, sc, os);
        }
    }
    __syncthreads();

    // ---- 6. row sums of posterior stds (8-way fp64 accumulators) ----
    for (int i = tid; i < n; i += NT) {
        double a0 = 0.0, a1 = 0.0, a2 = 0.0, a3 = 0.0;
        double a4 = 0.0, a5 = 0.0, a6 = 0.0, a7 = 0.0;
        int j = 0;
        for (; j + 7 < n; j += 8) {
            a0 += (double)W_[i][j];
            a1 += (double)W_[i][j + 1];
            a2 += (double)W_[i][j + 2];
            a3 += (double)W_[i][j + 3];
            a4 += (double)W_[i][j + 4];
            a5 += (double)W_[i][j + 5];
            a6 += (double)W_[i][j + 6];
            a7 += (double)W_[i][j + 7];
        }
        for (; j < n; j++) a0 += (double)W_[i][j];
        sums[i] = ((a0 + a1) + (a2 + a3)) + ((a4 + a5) + (a6 + a7));
    }
    __syncthreads();

    // ---- 7. gains + block-wide fp64 inclusive scan (shuffles) ----
    double g = 0.0;
    if (tid < n) {
        double prevs = (tid == 0) ? sqrt(osd) * (double)n : sums[tid - 1];
        g = prevs - sums[tid];
        if (g < 0.0) g = 0.0;
    }
    double x = g;
    #pragma unroll
    for (int off = 1; off < 32; off <<= 1) {
        double y = __shfl_up_sync(0xffffffffu, x, off);
        if (lane >= off) x += y;
    }
    if (lane == 31) warptot[warp] = x;
    __syncthreads();
    double woff = 0.0;
    for (int w2i = 0; w2i < warp; w2i++) woff += warptot[w2i];
    x += woff;
    double totcg = 0.0;
    #pragma unroll
    for (int w2i = 0; w2i < NWARP; w2i++) totcg += warptot[w2i];
    if (totcg < 1e-12) totcg = 1e-12;

    // ---- 8. group assignment + scatter ----
    if (tid < n) {
        double frac = (x - 0.5 * g) / totcg;
        int gbin = (int)floor(frac * (double)K);
        gbin = gbin < 0 ? 0 : (gbin > K - 1 ? K - 1 : gbin);
        int l = oidx[tid];
        size_t row = (size_t)(b * L_FIXED + l);
        outmask[row * (size_t)(V * K) + (size_t)(v * K + gbin)] = 1.0f;
        outgains[row] = (float)g;
    }
}

extern "C" void kernel_launch(void* const* d_in, const int* in_sizes, int n_in,
                              void* d_out, int out_size) {
    const float* t       = (const float*)d_in[0];
    const int*   vid     = (const int*)d_in[2];
    const float* noise   = (const float*)d_in[3];
    const float* outsc   = (const float*)d_in[4];
    const float* lensc   = (const float*)d_in[5];
    const float* alph    = (const float*)d_in[6];

    int BL = in_sizes[0];            // B*L
    int V  = in_sizes[3];
    int L  = L_FIXED;
    int B  = BL / L;
    int VK1 = out_size / BL;         // V*K + 1
    int K  = (VK1 - 1) / V;

    float* outp  = (float*)d_out;
    float* gains = outp + (size_t)BL * (size_t)(VK1 - 1);

    dim3 grid(V, B);
    gp_group_kernel<<<grid, NT>>>(t, vid, noise, outsc, lensc, alph,
                                  outp, gains, B, L, V, K);
}

// round 17
// speedup vs baseline: 2.1197x; 1.0430x over previous
#include <cuda_runtime.h>
#include <math.h>

// Fixed dataset shape: B=8, L=512, V=16, K=8.
// out = concat(mask[B,L,V*K], gains[B,L]) as float32.

#define NT 256
#define NWARP (NT / 32)
#define MAXN 64
#define L_FIXED 512
#define NCHUNK (L_FIXED / 32)
#define CSTRIDE (MAXN + 1)

// Forward-solve a 32-row block for one RHS column j against the RAW (LDL-style)
// factor: wi2 = w[i]/d_i, v_i^2 = w[i]*wi2, update w[r] -= Craw[r][i]*wi2.
// Zero padding (invd2=0, C pad=0) makes pad iterations exact no-ops.
// cum carried as Kahan-compensated fp32 pair (s, c), pairwise (2 elems/link).
// Writes wi2 to Vb (for raw coupling) and posterior stds to W[off+.][j].
__device__ __noinline__ float2 solve32_block(
    const float (*__restrict__ C)[CSTRIDE],
    float (*__restrict__ W)[CSTRIDE],
    float (*__restrict__ Vb)[CSTRIDE],
    const float* __restrict__ invd2,
    int off, int j, float2 sc, float os)
{
    float w[32], wsq[32];
#pragma unroll
    for (int r = 0; r < 32; r++) w[r] = W[off + r][j];
#pragma unroll
    for (int i = 0; i < 32; i++) {
        float wi2 = w[i] * invd2[off + i];
        wsq[i] = w[i] * wi2;                 // = v_i^2 >= 0
        Vb[i][j] = wi2;
#pragma unroll
        for (int r = i + 1; r < 32; r++)
            w[r] -= C[off + r][off + i] * wi2;
    }
    float s = sc.x, c = sc.y;
#pragma unroll
    for (int i = 0; i < 32; i += 2) {
        float a = wsq[i];
        float pair = a + wsq[i + 1];         // off-chain
        float ce = s + (c + a);              // even prefix estimate
        float yy = c + pair;
        float tt = s + yy;
        c = (s - tt) + yy;                   // Kahan compensation
        s = tt;
        W[off + i][j]     = sqrtf(fmaxf(os - ce, 1e-12f));
        W[off + i + 1][j] = sqrtf(fmaxf(os - (s + c), 1e-12f));
    }
    return make_float2(s, c);
}

__global__ __launch_bounds__(NT)
void gp_group_kernel(const float* __restrict__ t,
                     const int* __restrict__ vid,
                     const float* __restrict__ noise,
                     const float* __restrict__ outscale,
                     const float* __restrict__ lenscale,
                     const float* __restrict__ alpha,
                     float* __restrict__ outmask,
                     float* __restrict__ outgains,
                     int B, int L, int V, int K) {
    __shared__ float  C_[MAXN][CSTRIDE];
    __shared__ float  W_[MAXN][CSTRIDE];
    __shared__ float  Vb[32][CSTRIDE];
    __shared__ float  colA[MAXN];       // pivot-column double buffer (even k)
    __shared__ float  colB[MAXN];       // pivot-column double buffer (odd k)
    __shared__ float  ts[MAXN];
    __shared__ float  tsu[MAXN];
    __shared__ float  invd2[MAXN];
    __shared__ double sums[MAXN];
    __shared__ double warptot[NWARP];
    __shared__ int    oidx[MAXN];
    __shared__ int    tmpidx[MAXN];
    __shared__ int    nsh;

    const int v = blockIdx.x;
    const int b = blockIdx.y;
    const int tid = threadIdx.x;
    const int lane = tid & 31;
    const int warp = tid >> 5;

    const float* trow = t + (size_t)b * L_FIXED;
    const int* vrow = vid + (size_t)b * L_FIXED;

    // ---- 0. zero this CTA's mask columns: mask[b, :, v*K .. v*K+7] ----
    {
        float4 z = make_float4(0.f, 0.f, 0.f, 0.f);
        float* base = outmask + ((size_t)b * L_FIXED) * (size_t)(V * K) + (size_t)(v * K);
        #pragma unroll
        for (int l = tid; l < L_FIXED; l += NT) {
            float4* p = (float4*)(base + (size_t)l * (V * K));
            p[0] = z; p[1] = z;
        }
    }

    // ---- 1. order-preserving compaction (warp 0), prefetched loads ----
    if (warp == 0) {
        int   myv[NCHUNK];
        float myt[NCHUNK];
        #pragma unroll
        for (int c = 0; c < NCHUNK; c++) {
            int i = c * 32 + lane;
            myv[c] = vrow[i];
            myt[c] = trow[i];
        }
        int cnt = 0;
        #pragma unroll
        for (int c = 0; c < NCHUNK; c++) {
            bool p = (myv[c] == v);
            unsigned m = __ballot_sync(0xffffffffu, p);
            if (p) {
                int pos = cnt + __popc(m & ((1u << lane) - 1u));
                if (pos < MAXN) {
                    tmpidx[pos] = c * 32 + lane;
                    tsu[pos] = myt[c];
                }
            }
            cnt += __popc(m);
        }
        if (lane == 0) nsh = (cnt < MAXN) ? cnt : MAXN;
    }
    __syncthreads();
    const int n = nsh;
    if (n == 0) return;

    // ---- 2. stable rank sort by time ----
    if (tid < n) {
        float tj = tsu[tid];
        int r = 0;
        #pragma unroll 4
        for (int k2 = 0; k2 < n; k2++) {
            float tk = tsu[k2];
            r += (tk < tj) || (tk == tj && k2 < tid);
        }
        ts[r] = tj;
        oidx[r] = tmpidx[tid];
    }
    __syncthreads();

    const float  os  = outscale[v];
    const float  nz  = noise[v];
    const float  lsv = lenscale[v];
    const float  al  = alpha[v];
    const float  inv2al2 = 1.0f / (2.0f * al * lsv * lsv);
    const double osd = (double)os;

    // ---- 3. fill Kn (C_) and Kxx (W_) over the FULL 64x64, zero padding ----
    for (int idx = tid; idx < MAXN * MAXN; idx += NT) {
        int i = idx >> 6;
        int j = idx & (MAXN - 1);
        if (i < n && j < n) {
            if (i < j) {
                float d = ts[i] - ts[j];
                float kij = os * __expf(-al * __logf(1.0f + d * d * inv2al2));
                C_[i][j] = kij; C_[j][i] = kij;
                W_[i][j] = kij; W_[j][i] = kij;
            } else if (i == j) {
                C_[i][i] = os + nz + 1e-5f;
                W_[i][i] = os;
            }
        } else {
            C_[i][j] = 0.0f;
            W_[i][j] = 0.0f;
        }
    }
    __syncthreads();
    // seed pivot-column buffer for k=0 (cur = colA)
    for (int jj = tid; jj < MAXN; jj += NT) colA[jj] = C_[jj][0];
    __syncthreads();

    // ---- 4/5. Cholesky + forward solve, warp-specialized overlap ----
    // Convention: step k reads cur = (k&1)?colB:colA, writes nxt = other.
    // Each active thread peels j=k+1: writes new value to C_ AND nxt[row],
    // so the next step's pivot column lives in a distinct array (no aliasing
    // with the C_ store stream -> ptxas pipelines the inner loop).
    // Stage 1: steps with >32 active rows -> warps 0-1 (64 threads).
    if (warp < 2) {
        for (int k = 0; k < n - 33; k++) {
            const float* __restrict__ cur = (k & 1) ? colB : colA;
            float* __restrict__ nxt       = (k & 1) ? colA : colB;
            float invd = __fdividef(1.0f, cur[k]);
            int i = k + 1 + tid;
            if (i < n) {
                float cik = cur[i] * invd;
                float val1 = C_[i][k + 1] - cik * cur[k + 1];
                C_[i][k + 1] = val1;
                nxt[i] = val1;
                #pragma unroll 4
                for (int j = k + 2; j <= i; j++)
                    C_[i][j] -= cik * cur[j];
            }
            asm volatile("bar.sync 1, 64;" ::: "memory");
        }
    }
    // Stage 2: steps up to k=31 (<=32 active rows) -> warp 0 only.
    if (warp == 0) {
        const int kStart2 = (n > 33) ? (n - 33) : 0;
        const int kEnd2   = (n > 32) ? 31 : (n - 2);
        for (int k = kStart2; k <= kEnd2; k++) {
            const float* __restrict__ cur = (k & 1) ? colB : colA;
            float* __restrict__ nxt       = (k & 1) ? colA : colB;
            float invd = __fdividef(1.0f, cur[k]);
            int i = k + 1 + lane;
            if (i < n) {
                float cik = cur[i] * invd;
                float val1 = C_[i][k + 1] - cik * cur[k + 1];
                C_[i][k + 1] = val1;
                nxt[i] = val1;
                #pragma unroll 4
                for (int j = k + 2; j <= i; j++)
                    C_[i][j] -= cik * cur[j];
            }
            __syncwarp();
        }
    }
    // Leading 32x32 factor final -> warps 0,2,3 rendezvous (96 threads).
    // Warps 1 and 4-7 go to the convergent __syncthreads below.
    if (warp < 4 && warp != 1) {
        asm volatile("bar.sync 2, 96;" ::: "memory");
    }
    if (warp == 0) {
        // Stage 3 (concurrent with solve block 1): tail steps k=32..n-2.
        if (n > 32) {
            for (int k = 32; k <= n - 2; k++) {
                const float* __restrict__ cur = (k & 1) ? colB : colA;
                float* __restrict__ nxt       = (k & 1) ? colA : colB;
                float invd = __fdividef(1.0f, cur[k]);
                int i = k + 1 + lane;
                if (i < n) {
                    float cik = cur[i] * invd;
                    float val1 = C_[i][k + 1] - cik * cur[k + 1];
                    C_[i][k + 1] = val1;
                    nxt[i] = val1;
                    #pragma unroll 4
                    for (int j = k + 2; j <= i; j++)
                        C_[i][j] -= cik * cur[j];
                }
                __syncwarp();
            }
            int kk = 32 + lane;
            invd2[kk] = (kk < n) ? __fdividef(1.0f, C_[kk][kk]) : 0.0f;
            asm volatile("bar.sync 3, 96;" ::: "memory");
        }
    } else if (warp == 2 || warp == 3) {
        const int j = tid - 64;                   // solve column
        if (warp == 2)
            invd2[lane] = (lane < n) ? __fdividef(1.0f, C_[lane][lane]) : 0.0f;
        asm volatile("bar.sync 4, 64;" ::: "memory");   // warps 2-3
        float2 sc = make_float2(0.0f, 0.0f);
        if (j < n)
            sc = solve32_block(C_, W_, Vb, invd2, 0, j, sc, os);
        if (n > 32) {
            if (j < n) {
                // coupling: residual k2 -= L21_raw @ v' (v' staged in Vb)
                float w2[32];
                #pragma unroll
                for (int r = 0; r < 32; r++) w2[r] = W_[32 + r][j];
                for (int i = 0; i < 32; i++) {
                    float vi = Vb[i][j];
                    #pragma unroll
                    for (int r = 0; r < 32; r++)
                        w2[r] -= C_[32 + r][i] * vi;
                }
                #pragma unroll
                for (int r = 0; r < 32; r++) W_[32 + r][j] = w2[r];
            }
            asm volatile("bar.sync 3, 96;" ::: "memory");  // factor+coupling done
            if (j < n)
                solve32_block(C_, W_, Vb, invd2, 32, j, sc, os);
        }
    }
    __syncthreads();

    // ---- 6. row sums of posterior stds (8-way fp64 accumulators) ----
    for (int i = tid; i < n; i += NT) {
        double a0 = 0.0, a1 = 0.0, a2 = 0.0, a3 = 0.0;
        double a4 = 0.0, a5 = 0.0, a6 = 0.0, a7 = 0.0;
        int j = 0;
        for (; j + 7 < n; j += 8) {
            a0 += (double)W_[i][j];
            a1 += (double)W_[i][j + 1];
            a2 += (double)W_[i][j + 2];
            a3 += (double)W_[i][j + 3];
            a4 += (double)W_[i][j + 4];
            a5 += (double)W_[i][j + 5];
            a6 += (double)W_[i][j + 6];
            a7 += (double)W_[i][j + 7];
        }
        for (; j < n; j++) a0 += (double)W_[i][j];
        sums[i] = ((a0 + a1) + (a2 + a3)) + ((a4 + a5) + (a6 + a7));
    }
    __syncthreads();

    // ---- 7. gains + block-wide fp64 inclusive scan (shuffles) ----
    double g = 0.0;
    if (tid < n) {
        double prevs = (tid == 0) ? sqrt(osd) * (double)n : sums[tid - 1];
        g = prevs - sums[tid];
        if (g < 0.0) g = 0.0;
    }
    double x = g;
    #pragma unroll
    for (int off = 1; off < 32; off <<= 1) {
        double y = __shfl_up_sync(0xffffffffu, x, off);
        if (lane >= off) x += y;
    }
    if (lane == 31) warptot[warp] = x;
    __syncthreads();
    double woff = 0.0;
    for (int w2i = 0; w2i < warp; w2i++) woff += warptot[w2i];
    x += woff;
    double totcg = 0.0;
    #pragma unroll
    for (int w2i = 0; w2i < NWARP; w2i++) totcg += warptot[w2i];
    if (totcg < 1e-12) totcg = 1e-12;

    // ---- 8. group assignment + scatter ----
    if (tid < n) {
        double frac = (x - 0.5 * g) / totcg;
        int gbin = (int)floor(frac * (double)K);
        gbin = gbin < 0 ? 0 : (gbin > K - 1 ? K - 1 : gbin);
        int l = oidx[tid];
        size_t row = (size_t)(b * L_FIXED + l);
        outmask[row * (size_t)(V * K) + (size_t)(v * K + gbin)] = 1.0f;
        outgains[row] = (float)g;
    }
}

extern "C" void kernel_launch(void* const* d_in, const int* in_sizes, int n_in,
                              void* d_out, int out_size) {
    const float* t       = (const float*)d_in[0];
    const int*   vid     = (const int*)d_in[2];
    const float* noise   = (const float*)d_in[3];
    const float* outsc   = (const float*)d_in[4];
    const float* lensc   = (const float*)d_in[5];
    const float* alph    = (const float*)d_in[6];

    int BL = in_sizes[0];            // B*L
    int V  = in_sizes[3];
    int L  = L_FIXED;
    int B  = BL / L;
    int VK1 = out_size / BL;         // V*K + 1
    int K  = (VK1 - 1) / V;

    float* outp  = (float*)d_out;
    float* gains = outp + (size_t)BL * (size_t)(VK1 - 1);

    dim3 grid(V, B);
    gp_group_kernel<<<grid, NT>>>(t, vid, noise, outsc, lensc, alph,
                                  outp, gains, B, L, V, K);
}